// round 15
// baseline (speedup 1.0000x reference)
#include <cuda_runtime.h>

// (4,4,3,192,192) fp32 -> (4,4,2,192,192): per-patch KDE entropies (R=3, h=0.1).
// R15: R14 rolling-window + partial row-sums, plus:
//  - __launch_bounds__(64,12): regs<=85 -> 12 blocks/SM -> single wave (1824/1776)
//  - next-row loads hoisted above window accumulation (latency overlap)
//  - diagonal 1.0 folded into within-row partials (fewer adds per window)

#define WW  192
#define HW  (192 * 192)
#define STRIP 5

#define CM     (-1.9537149f)      // log9 + 1.5*ln(2*pi*0.01)  (C=3 marginal)
#define CJ     (-6.1046541f)      // log9 + 3.0*ln(2*pi*0.01)  (C=6 joint)
#define LN2_9  (0.0770163534f)    // ln(2)/9
#define PSC2   (12.0112240f)      // sqrt(100*log2(e)): exp(-50*d2)=ex2(u.u'+nt+nt')

static __device__ __forceinline__ float fast_ex2(float x)
{ float r; asm("ex2.approx.ftz.f32 %0, %1;" : "=f"(r) : "f"(x)); return r; }

static __device__ __forceinline__ float fast_lg2(float x)
{ float r; asm("lg2.approx.f32 %0, %1;" : "=f"(r) : "f"(x)); return r; }

static __device__ __forceinline__ float prod9(const float s[9])
{
    return ((s[0] * s[1]) * (s[2] * s[3])) *
           ((s[4] * s[5]) * (s[6] * s[7])) * s[8];
}

// Load one image row (3 px x 3 chan) pre-scaled, plus -0.5|u|^2 per pixel.
static __device__ __forceinline__ void load_row(const float* __restrict__ gb,
                                                int y, float r[3][3], float ntr[3])
{
    #pragma unroll
    for (int c = 0; c < 3; ++c) {
        const float* p = gb + c * HW + y * WW;
        #pragma unroll
        for (int dx = 0; dx < 3; ++dx) r[dx][c] = p[dx] * PSC2;
    }
    #pragma unroll
    for (int dx = 0; dx < 3; ++dx) {
        float t = r[dx][0] * r[dx][0];
        t = fmaf(r[dx][1], r[dx][1], t);
        t = fmaf(r[dx][2], r[dx][2], t);
        ntr[dx] = -0.5f * t;
    }
}

static __device__ __forceinline__ float pair_e(const float* a, float na,
                                               const float* b, float nb)
{
    float v = fmaf(a[0], b[0], na);
    v = fmaf(a[1], b[1], v);
    v = fmaf(a[2], b[2], v);
    return fast_ex2(v + nb);
}

// Within-row group for one slot: per-pixel partials of its 2 pair-exps,
// WITH the diagonal 1.0 folded in.
static __device__ __forceinline__ void gen_within(const float r[3][3], const float ntr[3],
                                                  int src, float we[3], float wj[3])
{
    float e01 = pair_e(r[0], ntr[0], r[1], ntr[1]);
    float e02 = pair_e(r[0], ntr[0], r[2], ntr[2]);
    float e12 = pair_e(r[1], ntr[1], r[2], ntr[2]);
    float j01 = e01 * __shfl_sync(0xffffffffu, e01, src);
    float j02 = e02 * __shfl_sync(0xffffffffu, e02, src);
    float j12 = e12 * __shfl_sync(0xffffffffu, e12, src);
    we[0] = 1.0f + e01 + e02;  we[1] = 1.0f + e01 + e12;  we[2] = 1.0f + e02 + e12;
    wj[0] = 1.0f + j01 + j02;  wj[1] = 1.0f + j01 + j12;  wj[2] = 1.0f + j02 + j12;
}

// Cross group between slots sa (data ra) and sb (data rb): per-pixel partials.
// A-side = lower-numbered slot's pixels, B-side = higher.
static __device__ __forceinline__ void gen_cross(
    const float ra[3][3], const float nta[3], int sa,
    const float rb[3][3], const float ntb[3], int sb,
    int src,
    float cAe[3][3], float cBe[3][3], float cAj[3][3], float cBj[3][3])
{
    const int gid = sa + sb - 1;   // {0,1}->0, {0,2}->1, {1,2}->2
    float ge[3][3], gj[3][3];
    #pragma unroll
    for (int i = 0; i < 3; ++i)
        #pragma unroll
        for (int j = 0; j < 3; ++j) {
            float e = pair_e(ra[i], nta[i], rb[j], ntb[j]);
            ge[i][j] = e;
            gj[i][j] = e * __shfl_sync(0xffffffffu, e, src);
        }
    #pragma unroll
    for (int i = 0; i < 3; ++i) {
        float ae = ge[i][0] + ge[i][1] + ge[i][2];
        float be = ge[0][i] + ge[1][i] + ge[2][i];
        float aj = gj[i][0] + gj[i][1] + gj[i][2];
        float bj = gj[0][i] + gj[1][i] + gj[2][i];
        if (sa < sb) {
            cAe[gid][i] = ae;  cBe[gid][i] = be;
            cAj[gid][i] = aj;  cBj[gid][i] = bj;
        } else {
            cAe[gid][i] = be;  cBe[gid][i] = ae;
            cAj[gid][i] = bj;  cBj[gid][i] = aj;
        }
    }
}

// Partial for slot s's pixels from group {s,o}.
static __device__ __forceinline__ float pick(const float A[3][3], const float B[3][3],
                                             int s, int o, int i)
{
    const int g = s + o - 1;
    return (s < o) ? A[g][i] : B[g][i];
}

// Border ring zeroing for one patch's two output channels (cold path).
static __device__ __forceinline__ void zero_border(float* ob, int x, int y)
{
    if (y == 0)   { ob[x + 1] = 0.0f;            ob[HW + x + 1] = 0.0f; }
    if (y == 189) { ob[191*WW + x + 1] = 0.0f;   ob[HW + 191*WW + x + 1] = 0.0f; }
    if (x == 0) {
        ob[(y + 1) * WW] = 0.0f;                 ob[HW + (y + 1) * WW] = 0.0f;
        if (y == 0)   { ob[0] = 0.0f;            ob[HW] = 0.0f; }
        if (y == 189) { ob[191*WW] = 0.0f;       ob[HW + 191*WW] = 0.0f; }
    }
    if (x == 189) {
        ob[(y + 1) * WW + 191] = 0.0f;           ob[HW + (y + 1) * WW + 191] = 0.0f;
        if (y == 0)   { ob[191] = 0.0f;          ob[HW + 191] = 0.0f; }
        if (y == 189) { ob[191*WW + 191] = 0.0f; ob[HW + 191*WW + 191] = 0.0f; }
    }
}

__global__ void __launch_bounds__(64, 12)
je15_kernel(const float* __restrict__ in, float* __restrict__ out)
{
    int lane = threadIdx.x & 31;
    int warp = threadIdx.x >> 5;  // 0..1
    int sf   = lane & 3;          // frame handled by this lane
    int sub  = lane >> 2;         // patch-column slot within warp

    int x  = blockIdx.x * 16 + warp * 8 + sub;   // patch col (valid < 190)
    int y0 = blockIdx.y * STRIP;                 // strip start (190 = 38*5)
    int n  = blockIdx.z;

    bool valid = (x < 190);
    int  xc    = valid ? x : 189;                // clamp: lockstep shuffles

    const float* gb = in + ((size_t)(n * 4 + sf) * 3) * HW + xc;
    float* ob = out + ((size_t)(n * 4 + sf) * 2) * HW;
    int src = (sf == 3) ? lane : (lane + 1);     // frame 3 pairs with itself

    // Rolling state: 3 pixel rows + per-group partial row-sums.
    float q[3][3][3];   // [slot][col][chan]
    float nt[3][3];     // [slot][col]
    float we[3][3], wj[3][3];               // within-row partials (incl diag 1)
    float cAe[3][3], cBe[3][3];             // cross partials, A=lower slot side
    float cAj[3][3], cBj[3][3];

    load_row(gb, y0 + 0, q[0], nt[0]);
    load_row(gb, y0 + 1, q[1], nt[1]);
    load_row(gb, y0 + 2, q[2], nt[2]);
    gen_within(q[0], nt[0], src, we[0], wj[0]);
    gen_within(q[1], nt[1], src, we[1], wj[1]);
    gen_within(q[2], nt[2], src, we[2], wj[2]);
    gen_cross(q[0], nt[0], 0, q[1], nt[1], 1, src, cAe, cBe, cAj, cBj);
    gen_cross(q[0], nt[0], 0, q[2], nt[2], 2, src, cAe, cBe, cAj, cBj);
    gen_cross(q[1], nt[1], 1, q[2], nt[2], 2, src, cAe, cBe, cAj, cBj);

    #pragma unroll
    for (int t = 0; t < STRIP; ++t) {
        const int p0 = t % 3;            // window row 0 (oldest), compile-time
        const int p1 = (t + 1) % 3;
        const int p2 = (t + 2) % 3;      // youngest
        int y = y0 + t;

        // ---- hoisted next-row load: q[p0]/nt[p0] are NOT read below, so
        // overwriting them now overlaps LDG latency with the accumulation ----
        if (t < STRIP - 1)
            load_row(gb, y + 3, q[p0], nt[p0]);

        // ---- window accumulation: pure adds from stored partials ----
        float vm[9], vj[9];
        #pragma unroll
        for (int i = 0; i < 3; ++i) {
            vm[i]     = we[p0][i] + pick(cAe, cBe, p0, p1, i) + pick(cAe, cBe, p0, p2, i);
            vm[3 + i] = we[p1][i] + pick(cAe, cBe, p1, p0, i) + pick(cAe, cBe, p1, p2, i);
            vm[6 + i] = we[p2][i] + pick(cAe, cBe, p2, p0, i) + pick(cAe, cBe, p2, p1, i);
            vj[i]     = wj[p0][i] + pick(cAj, cBj, p0, p1, i) + pick(cAj, cBj, p0, p2, i);
            vj[3 + i] = wj[p1][i] + pick(cAj, cBj, p1, p0, i) + pick(cAj, cBj, p1, p2, i);
            vj[6 + i] = wj[p2][i] + pick(cAj, cBj, p2, p0, i) + pick(cAj, cBj, p2, p1, i);
        }
        float hm = fmaf(-LN2_9, fast_lg2(prod9(vm)), CM);
        float hj = fmaf(-LN2_9, fast_lg2(prod9(vj)), CJ);

        if (valid) {
            int o = (y + 1) * WW + (x + 1);
            ob[o]      = hm;
            ob[HW + o] = hj;
            zero_border(ob, x, y);
        }

        // ---- regenerate groups for the slot now holding the new row ----
        if (t < STRIP - 1) {
            gen_within(q[p0], nt[p0], src, we[p0], wj[p0]);
            gen_cross(q[p1], nt[p1], p1, q[p0], nt[p0], p0, src, cAe, cBe, cAj, cBj);
            gen_cross(q[p2], nt[p2], p2, q[p0], nt[p0], p0, src, cAe, cBe, cAj, cBj);
        }
    }
}

extern "C" void kernel_launch(void* const* d_in, const int* in_sizes, int n_in,
                              void* d_out, int out_size)
{
    dim3 blk(64, 1, 1);
    dim3 grd(12, 38, 4);  // 12 blocks x 16 cols = 192 (190 valid); 38 strips; 4 batches
    je15_kernel<<<grd, blk>>>((const float*)d_in[0], (float*)d_out);
}

// round 17
// speedup vs baseline: 1.0408x; 1.0408x over previous
#include <cuda_runtime.h>

// (4,4,3,192,192) fp32 -> (4,4,2,192,192): per-patch KDE entropies (R=3, h=0.1).
// R16: exact R14 body (rolling window + partial row-sums, 96 regs) with
// STRIP=6 / 32 y-blocks: grid 1536 vs 10-blocks/SM capacity 1480 -> 1.04 waves
// (was 1824 -> 1.23). Rows beyond 189 are computed on clamped loads, not stored.

#define WW  192
#define HW  (192 * 192)
#define STRIP 6

#define CM     (-1.9537149f)      // log9 + 1.5*ln(2*pi*0.01)  (C=3 marginal)
#define CJ     (-6.1046541f)      // log9 + 3.0*ln(2*pi*0.01)  (C=6 joint)
#define LN2_9  (0.0770163534f)    // ln(2)/9
#define PSC2   (12.0112240f)      // sqrt(100*log2(e)): exp(-50*d2)=ex2(u.u'+nt+nt')

static __device__ __forceinline__ float fast_ex2(float x)
{ float r; asm("ex2.approx.ftz.f32 %0, %1;" : "=f"(r) : "f"(x)); return r; }

static __device__ __forceinline__ float fast_lg2(float x)
{ float r; asm("lg2.approx.f32 %0, %1;" : "=f"(r) : "f"(x)); return r; }

static __device__ __forceinline__ float prod9(const float s[9])
{
    return ((s[0] * s[1]) * (s[2] * s[3])) *
           ((s[4] * s[5]) * (s[6] * s[7])) * s[8];
}

// Load one image row (3 px x 3 chan) pre-scaled, plus -0.5|u|^2 per pixel.
static __device__ __forceinline__ void load_row(const float* __restrict__ gb,
                                                int y, float r[3][3], float ntr[3])
{
    #pragma unroll
    for (int c = 0; c < 3; ++c) {
        const float* p = gb + c * HW + y * WW;
        #pragma unroll
        for (int dx = 0; dx < 3; ++dx) r[dx][c] = p[dx] * PSC2;
    }
    #pragma unroll
    for (int dx = 0; dx < 3; ++dx) {
        float t = r[dx][0] * r[dx][0];
        t = fmaf(r[dx][1], r[dx][1], t);
        t = fmaf(r[dx][2], r[dx][2], t);
        ntr[dx] = -0.5f * t;
    }
}

static __device__ __forceinline__ float pair_e(const float* a, float na,
                                               const float* b, float nb)
{
    float v = fmaf(a[0], b[0], na);
    v = fmaf(a[1], b[1], v);
    v = fmaf(a[2], b[2], v);
    return fast_ex2(v + nb);
}

// Within-row group for one slot: per-pixel partial sums of its 2 pair-exps.
static __device__ __forceinline__ void gen_within(const float r[3][3], const float ntr[3],
                                                  int src, float we[3], float wj[3])
{
    float e01 = pair_e(r[0], ntr[0], r[1], ntr[1]);
    float e02 = pair_e(r[0], ntr[0], r[2], ntr[2]);
    float e12 = pair_e(r[1], ntr[1], r[2], ntr[2]);
    float j01 = e01 * __shfl_sync(0xffffffffu, e01, src);
    float j02 = e02 * __shfl_sync(0xffffffffu, e02, src);
    float j12 = e12 * __shfl_sync(0xffffffffu, e12, src);
    we[0] = e01 + e02;  we[1] = e01 + e12;  we[2] = e02 + e12;
    wj[0] = j01 + j02;  wj[1] = j01 + j12;  wj[2] = j02 + j12;
}

// Cross group between slots sa (data ra) and sb (data rb): store per-pixel
// partial row-sums. A-side = lower-numbered slot's pixels, B-side = higher.
static __device__ __forceinline__ void gen_cross(
    const float ra[3][3], const float nta[3], int sa,
    const float rb[3][3], const float ntb[3], int sb,
    int src,
    float cAe[3][3], float cBe[3][3], float cAj[3][3], float cBj[3][3])
{
    const int gid = sa + sb - 1;   // {0,1}->0, {0,2}->1, {1,2}->2
    float ge[3][3], gj[3][3];
    #pragma unroll
    for (int i = 0; i < 3; ++i)
        #pragma unroll
        for (int j = 0; j < 3; ++j) {
            float e = pair_e(ra[i], nta[i], rb[j], ntb[j]);
            ge[i][j] = e;
            gj[i][j] = e * __shfl_sync(0xffffffffu, e, src);
        }
    #pragma unroll
    for (int i = 0; i < 3; ++i) {
        float ae = ge[i][0] + ge[i][1] + ge[i][2];        // ra-pixel i partial
        float be = ge[0][i] + ge[1][i] + ge[2][i];        // rb-pixel i partial
        float aj = gj[i][0] + gj[i][1] + gj[i][2];
        float bj = gj[0][i] + gj[1][i] + gj[2][i];
        if (sa < sb) {
            cAe[gid][i] = ae;  cBe[gid][i] = be;
            cAj[gid][i] = aj;  cBj[gid][i] = bj;
        } else {
            cAe[gid][i] = be;  cBe[gid][i] = ae;
            cAj[gid][i] = bj;  cBj[gid][i] = aj;
        }
    }
}

// Partial for slot s's pixels from group {s,o}.
static __device__ __forceinline__ float pick(const float A[3][3], const float B[3][3],
                                             int s, int o, int i)
{
    const int g = s + o - 1;
    return (s < o) ? A[g][i] : B[g][i];
}

// Border ring zeroing for one patch's two output channels (cold path).
static __device__ __forceinline__ void zero_border(float* ob, int x, int y)
{
    if (y == 0)   { ob[x + 1] = 0.0f;            ob[HW + x + 1] = 0.0f; }
    if (y == 189) { ob[191*WW + x + 1] = 0.0f;   ob[HW + 191*WW + x + 1] = 0.0f; }
    if (x == 0) {
        ob[(y + 1) * WW] = 0.0f;                 ob[HW + (y + 1) * WW] = 0.0f;
        if (y == 0)   { ob[0] = 0.0f;            ob[HW] = 0.0f; }
        if (y == 189) { ob[191*WW] = 0.0f;       ob[HW + 191*WW] = 0.0f; }
    }
    if (x == 189) {
        ob[(y + 1) * WW + 191] = 0.0f;           ob[HW + (y + 1) * WW + 191] = 0.0f;
        if (y == 0)   { ob[191] = 0.0f;          ob[HW + 191] = 0.0f; }
        if (y == 189) { ob[191*WW + 191] = 0.0f; ob[HW + 191*WW + 191] = 0.0f; }
    }
}

__global__ void __launch_bounds__(64)
je16_kernel(const float* __restrict__ in, float* __restrict__ out)
{
    int lane = threadIdx.x & 31;
    int warp = threadIdx.x >> 5;  // 0..1
    int sf   = lane & 3;          // frame handled by this lane
    int sub  = lane >> 2;         // patch-column slot within warp

    int x  = blockIdx.x * 16 + warp * 8 + sub;   // patch col (valid < 190)
    int y0 = blockIdx.y * STRIP;                 // strip start (32 strips x 6 = 192)
    int n  = blockIdx.z;

    bool xvalid = (x < 190);
    int  xc     = xvalid ? x : 189;              // clamp: lockstep shuffles

    const float* gb = in + ((size_t)(n * 4 + sf) * 3) * HW + xc;
    float* ob = out + ((size_t)(n * 4 + sf) * 2) * HW;
    int src = (sf == 3) ? lane : (lane + 1);     // frame 3 pairs with itself

    // Rolling state: 3 pixel rows + per-group partial row-sums.
    float q[3][3][3];   // [slot][col][chan]
    float nt[3][3];     // [slot][col]
    float we[3][3], wj[3][3];               // within-row partials per slot
    float cAe[3][3], cBe[3][3];             // cross partials, A=lower slot side
    float cAj[3][3], cBj[3][3];

    load_row(gb, y0 + 0, q[0], nt[0]);
    load_row(gb, y0 + 1, q[1], nt[1]);
    load_row(gb, y0 + 2, q[2], nt[2]);
    gen_within(q[0], nt[0], src, we[0], wj[0]);
    gen_within(q[1], nt[1], src, we[1], wj[1]);
    gen_within(q[2], nt[2], src, we[2], wj[2]);
    gen_cross(q[0], nt[0], 0, q[1], nt[1], 1, src, cAe, cBe, cAj, cBj);
    gen_cross(q[0], nt[0], 0, q[2], nt[2], 2, src, cAe, cBe, cAj, cBj);
    gen_cross(q[1], nt[1], 1, q[2], nt[2], 2, src, cAe, cBe, cAj, cBj);

    #pragma unroll
    for (int t = 0; t < STRIP; ++t) {
        const int p0 = t % 3;            // window row 0 (oldest), compile-time
        const int p1 = (t + 1) % 3;
        const int p2 = (t + 2) % 3;      // youngest
        int y = y0 + t;

        // ---- window accumulation: pure adds from stored partials ----
        float vm[9], vj[9];
        #pragma unroll
        for (int i = 0; i < 3; ++i) {
            vm[i]     = 1.0f + we[p0][i] + pick(cAe, cBe, p0, p1, i) + pick(cAe, cBe, p0, p2, i);
            vm[3 + i] = 1.0f + we[p1][i] + pick(cAe, cBe, p1, p0, i) + pick(cAe, cBe, p1, p2, i);
            vm[6 + i] = 1.0f + we[p2][i] + pick(cAe, cBe, p2, p0, i) + pick(cAe, cBe, p2, p1, i);
            vj[i]     = 1.0f + wj[p0][i] + pick(cAj, cBj, p0, p1, i) + pick(cAj, cBj, p0, p2, i);
            vj[3 + i] = 1.0f + wj[p1][i] + pick(cAj, cBj, p1, p0, i) + pick(cAj, cBj, p1, p2, i);
            vj[6 + i] = 1.0f + wj[p2][i] + pick(cAj, cBj, p2, p0, i) + pick(cAj, cBj, p2, p1, i);
        }
        float hm = CM - LN2_9 * fast_lg2(prod9(vm));
        float hj = CJ - LN2_9 * fast_lg2(prod9(vj));

        if (xvalid && y < 190) {
            int o = (y + 1) * WW + (x + 1);
            ob[o]      = hm;
            ob[HW + o] = hj;
            zero_border(ob, x, y);
        }

        // ---- slide: new row replaces expiring slot p0 (row index clamped) ----
        if (t < STRIP - 1) {
            int yn = y + 3; if (yn > 191) yn = 191;
            load_row(gb, yn, q[p0], nt[p0]);
            gen_within(q[p0], nt[p0], src, we[p0], wj[p0]);
            gen_cross(q[p1], nt[p1], p1, q[p0], nt[p0], p0, src, cAe, cBe, cAj, cBj);
            gen_cross(q[p2], nt[p2], p2, q[p0], nt[p0], p0, src, cAe, cBe, cAj, cBj);
        }
    }
}

extern "C" void kernel_launch(void* const* d_in, const int* in_sizes, int n_in,
                              void* d_out, int out_size)
{
    dim3 blk(64, 1, 1);
    dim3 grd(12, 32, 4);  // 12 x-blocks x 16 cols; 32 strips x 6 rows (190 valid); 4 batches
    je16_kernel<<<grd, blk>>>((const float*)d_in[0], (float*)d_out);
}